// round 16
// baseline (speedup 1.0000x reference)
#include <cuda_runtime.h>
#include <cstdint>

#define B_ 8
#define L_ 256
#define D_ 256
#define CH 32

// 64 MB scratch for h = relu(z @ W1 + b1) * mask   [B][L][L][CH]
__device__ float g_h[(size_t)B_ * L_ * L_ * CH];

// ---------- packed f32x2 helpers (sm_103a) ----------
__device__ __forceinline__ unsigned long long ffma2(unsigned long long a,
                                                    unsigned long long b,
                                                    unsigned long long c) {
    unsigned long long d;
    asm("fma.rn.f32x2 %0, %1, %2, %3;" : "=l"(d) : "l"(a), "l"(b), "l"(c));
    return d;
}
__device__ __forceinline__ unsigned long long dup2(float x) {
    unsigned long long d;
    asm("mov.b64 %0, {%1, %1};" : "=l"(d) : "f"(x));
    return d;
}
__device__ __forceinline__ float2 unpk(unsigned long long v) {
    float2 r;
    asm("mov.b64 {%0, %1}, %2;" : "=f"(r.x), "=f"(r.y) : "l"(v));
    return r;
}

// ============================================================
// Stage 1 with SYMMETRY: h[b,i,j,:] == h[b,j,i,:]. (unchanged from R10;
// measured at 97% of the fp32 FLOP roofline)
// ============================================================
__global__ __launch_bounds__(128, 2)
void stage1_kernel(const float* __restrict__ x, const int* __restrict__ plen_g,
                   const float* __restrict__ W1, const float* __restrict__ b1) {
    extern __shared__ float smem[];
    float* sWm = smem;                 // 128 x 32 (mul weights, current half)
    float* sWs = smem + 4096;          // 128 x 32 (sub weights, current half)
    float* sxi = smem + 8192;          // 16 rows * 257
    float* sxj = sxi + 16 * 257;       // 32 rows * 257

    const int i0 = blockIdx.y * 16;
    const int j0 = blockIdx.x * 32;

    if (i0 >= j0 + 32) return;                 // strictly-lower: mirrored by partner
    const bool upper = (i0 + 16 <= j0);        // store mirror too

    const int b  = blockIdx.z;
    const int tid = threadIdx.x;
    const int ti = tid >> 4;           // 0..7
    const int tj = tid & 15;           // 0..15
    const int plen = plen_g[b];

    const int gis[2] = {i0 + ti, i0 + ti + 8};
    const int gjs[2] = {j0 + tj, j0 + tj + 16};

    float* h_base = g_h + (size_t)b * L_ * L_ * CH;

    if (i0 >= plen || j0 >= plen) {    // fully masked: zero own (+mirror), bail
        float4 z = make_float4(0.f, 0.f, 0.f, 0.f);
        #pragma unroll
        for (int pi = 0; pi < 2; pi++)
            #pragma unroll
            for (int pj = 0; pj < 2; pj++) {
                float4* op = reinterpret_cast<float4*>(
                    h_base + ((size_t)gis[pi] * L_ + gjs[pj]) * CH);
                #pragma unroll
                for (int k = 0; k < 8; k++) op[k] = z;
                if (upper) {
                    float4* om = reinterpret_cast<float4*>(
                        h_base + ((size_t)gjs[pj] * L_ + gis[pi]) * CH);
                    #pragma unroll
                    for (int k = 0; k < 8; k++) om[k] = z;
                }
            }
        return;
    }

    // stage x tiles (float4 global loads, scalar smem stores; stride 257)
    {
        const float* xb = x + (size_t)b * L_ * D_;
        const float4* xb4 = reinterpret_cast<const float4*>(xb);
        #pragma unroll
        for (int it = 0; it < 8; it++) {           // 16*64 float4
            int idx = tid + it * 128;
            int r = idx >> 6, c = (idx & 63) * 4;
            float4 v = xb4[(i0 + r) * 64 + (c >> 2)];
            float* d0 = sxi + r * 257 + c;
            d0[0] = v.x; d0[1] = v.y; d0[2] = v.z; d0[3] = v.w;
        }
        #pragma unroll
        for (int it = 0; it < 16; it++) {          // 32*64 float4
            int idx = tid + it * 128;
            int r = idx >> 6, c = (idx & 63) * 4;
            float4 v = xb4[(j0 + r) * 64 + (c >> 2)];
            float* d0 = sxj + r * 257 + c;
            d0[0] = v.x; d0[1] = v.y; d0[2] = v.z; d0[3] = v.w;
        }
    }

    unsigned long long acc[4][16];
    #pragma unroll
    for (int p = 0; p < 4; p++)
        #pragma unroll
        for (int k = 0; k < 16; k++) acc[p][k] = 0ULL;

    const float* xi0 = sxi + ti * 257;
    const float* xi1 = sxi + (ti + 8) * 257;
    const float* xj0 = sxj + tj * 257;
    const float* xj1 = sxj + (tj + 16) * 257;

    for (int half = 0; half < 2; half++) {
        if (half) __syncthreads();
        {
            const float4* wm4 = reinterpret_cast<const float4*>(W1 + half * 128 * 32);
            const float4* ws4 = reinterpret_cast<const float4*>(W1 + (256 + half * 128) * 32);
            float4* sm4 = reinterpret_cast<float4*>(sWm);
            float4* ss4 = reinterpret_cast<float4*>(sWs);
            #pragma unroll
            for (int k = 0; k < 8; k++) {
                sm4[tid + k * 128] = wm4[tid + k * 128];
                ss4[tid + k * 128] = ws4[tid + k * 128];
            }
        }
        __syncthreads();

        const int dof = half * 128;
        #pragma unroll 2
        for (int dd = 0; dd < 128; dd++) {
            float a0 = xi0[dof + dd], a1 = xi1[dof + dd];
            float c0 = xj0[dof + dd], c1 = xj1[dof + dd];
            unsigned long long p00 = dup2(a0 * c0);
            unsigned long long p01 = dup2(a0 * c1);
            unsigned long long p10 = dup2(a1 * c0);
            unsigned long long p11 = dup2(a1 * c1);
            unsigned long long s00 = dup2(fabsf(a0 - c0));
            unsigned long long s01 = dup2(fabsf(a0 - c1));
            unsigned long long s10 = dup2(fabsf(a1 - c0));
            unsigned long long s11 = dup2(fabsf(a1 - c1));
            const ulonglong2* wm = reinterpret_cast<const ulonglong2*>(sWm + dd * 32);
            const ulonglong2* ws = reinterpret_cast<const ulonglong2*>(sWs + dd * 32);
            #pragma unroll
            for (int k = 0; k < 8; k++) {
                ulonglong2 M = wm[k];      // LDS.128, warp-uniform broadcast
                ulonglong2 S = ws[k];
                acc[0][2*k]   = ffma2(p00, M.x, acc[0][2*k]);
                acc[0][2*k+1] = ffma2(p00, M.y, acc[0][2*k+1]);
                acc[1][2*k]   = ffma2(p01, M.x, acc[1][2*k]);
                acc[1][2*k+1] = ffma2(p01, M.y, acc[1][2*k+1]);
                acc[2][2*k]   = ffma2(p10, M.x, acc[2][2*k]);
                acc[2][2*k+1] = ffma2(p10, M.y, acc[2][2*k+1]);
                acc[3][2*k]   = ffma2(p11, M.x, acc[3][2*k]);
                acc[3][2*k+1] = ffma2(p11, M.y, acc[3][2*k+1]);
                acc[0][2*k]   = ffma2(s00, S.x, acc[0][2*k]);
                acc[0][2*k+1] = ffma2(s00, S.y, acc[0][2*k+1]);
                acc[1][2*k]   = ffma2(s01, S.x, acc[1][2*k]);
                acc[1][2*k+1] = ffma2(s01, S.y, acc[1][2*k+1]);
                acc[2][2*k]   = ffma2(s10, S.x, acc[2][2*k]);
                acc[2][2*k+1] = ffma2(s10, S.y, acc[2][2*k+1]);
                acc[3][2*k]   = ffma2(s11, S.x, acc[3][2*k]);
                acc[3][2*k+1] = ffma2(s11, S.y, acc[3][2*k+1]);
            }
        }
    }

    // epilogue: bias + relu + mask; own store, plus mirror store if upper
    const float4* b4 = reinterpret_cast<const float4*>(b1);
    #pragma unroll
    for (int pi = 0; pi < 2; pi++) {
        #pragma unroll
        for (int pj = 0; pj < 2; pj++) {
            const int p = pi * 2 + pj;
            const bool valid = (gis[pi] < plen) && (gjs[pj] < plen);
            float4 o[8];
            #pragma unroll
            for (int k = 0; k < 8; k++) {
                if (valid) {
                    float2 lo = unpk(acc[p][2*k]);
                    float2 hi = unpk(acc[p][2*k+1]);
                    float4 bias = __ldg(b4 + k);
                    o[k].x = fmaxf(lo.x + bias.x, 0.f);
                    o[k].y = fmaxf(lo.y + bias.y, 0.f);
                    o[k].z = fmaxf(hi.x + bias.z, 0.f);
                    o[k].w = fmaxf(hi.y + bias.w, 0.f);
                } else {
                    o[k] = make_float4(0.f, 0.f, 0.f, 0.f);
                }
            }
            float4* op = reinterpret_cast<float4*>(
                h_base + ((size_t)gis[pi] * L_ + gjs[pj]) * CH);
            #pragma unroll
            for (int k = 0; k < 8; k++) op[k] = o[k];
            if (upper) {
                float4* om = reinterpret_cast<float4*>(
                    h_base + ((size_t)gjs[pj] * L_ + gis[pi]) * CH);
                #pragma unroll
                for (int k = 0; k < 8; k++) om[k] = o[k];
            }
        }
    }
}

// ============================================================
// Stage 2: 7x7x32->1 SAME conv + mask, f32x2 over channel pairs.
// 32x32 tile, 128 threads, 8 outputs/thread.
// OCCUPANCY FIX: unroll-1 on cp/di keeps ONE 14-wide window live
// (~100 regs vs 230); smem trimmed to exactly 57344 B -> 4 CTAs/SM.
// ============================================================
#define S2_W  42                   // u64 stride per halo row
#define S2_PL (38 * S2_W)          // u64 elems per pair-plane (1596)

__global__ __launch_bounds__(128, 4)
void stage2_kernel(const int* __restrict__ plen_g, const float* __restrict__ W2,
                   const float* __restrict__ b2, float* __restrict__ out) {
    extern __shared__ float smem[];
    float*  swf = smem;                                   // W2: 1568 floats
    float2* sh2 = reinterpret_cast<float2*>(smem + 1568); // 4 pair-planes (16B-aligned: 6272B)

    const int b  = blockIdx.z;
    const int i0 = blockIdx.y * 32;
    const int j0 = blockIdx.x * 32;
    const int tid = threadIdx.x;
    const int row = tid >> 2;              // 0..31
    const int jq  = (tid & 3) * 8;         // 0,8,16,24
    const int plen = plen_g[b];
    const int i = i0 + row;

    float4* outp = reinterpret_cast<float4*>(
        out + ((size_t)(b * L_ + i) * L_ + j0 + jq));

    if (i0 >= plen || j0 >= plen) {        // fully masked tile
        float4 z = make_float4(0.f, 0.f, 0.f, 0.f);
        outp[0] = z; outp[1] = z;
        return;
    }

    // stage W2 (contiguous channel pairs)
    {
        const float4* w4 = reinterpret_cast<const float4*>(W2);
        float4* s4 = reinterpret_cast<float4*>(swf);
        for (int idx = tid; idx < 392; idx += 128) s4[idx] = w4[idx];
    }
    const unsigned long long* swu = reinterpret_cast<const unsigned long long*>(swf);

    unsigned long long acc2[8];
    #pragma unroll
    for (int q = 0; q < 8; q++) acc2[q] = 0ULL;

    #pragma unroll 1
    for (int chunk = 0; chunk < 4; chunk++) {
        __syncthreads();   // weights staged (chunk 0) / prev chunk compute done
        // fill 38x38 halo: 8 channels per pixel -> 4 pair-planes
        for (int p = tid; p < 38 * 38; p += 128) {
            int rr = p / 38, cc = p - rr * 38;
            int rg = i0 - 3 + rr, cg = j0 - 3 + cc;
            float4 v0 = make_float4(0.f, 0.f, 0.f, 0.f);
            float4 v1 = v0;
            if ((unsigned)rg < L_ && (unsigned)cg < L_) {
                const float4* hp = reinterpret_cast<const float4*>(
                    g_h + ((size_t)(b * L_ + rg) * L_ + cg) * CH + chunk * 8);
                v0 = hp[0];
                v1 = hp[1];
            }
            float2* d0 = sh2 + rr * S2_W + cc;
            d0[0 * S2_PL] = make_float2(v0.x, v0.y);
            d0[1 * S2_PL] = make_float2(v0.z, v0.w);
            d0[2 * S2_PL] = make_float2(v1.x, v1.y);
            d0[3 * S2_PL] = make_float2(v1.z, v1.w);
        }
        __syncthreads();

        #pragma unroll 1
        for (int cp = 0; cp < 4; cp++) {
            const int gcp = chunk * 4 + cp;        // global channel-pair 0..15
            #pragma unroll 1
            for (int di = 0; di < 7; di++) {
                // 14-wide u64 sliding window: pixels jq..jq+13 (16B-aligned)
                const ulonglong2* wr = reinterpret_cast<const ulonglong2*>(
                    sh2 + cp * S2_PL + (row + di) * S2_W + jq);
                ulonglong2 a0 = wr[0], a1 = wr[1], a2 = wr[2], a3 = wr[3],
                           a4 = wr[4], a5 = wr[5], a6 = wr[6];
                unsigned long long win[14] = {a0.x, a0.y, a1.x, a1.y, a2.x, a2.y,
                                              a3.x, a3.y, a4.x, a4.y, a5.x, a5.y,
                                              a6.x, a6.y};
                const unsigned long long* wrow = swu + di * 7 * 16 + gcp;
                #pragma unroll
                for (int dj = 0; dj < 7; dj++) {
                    unsigned long long wp = wrow[dj * 16];   // uniform LDS.64
                    #pragma unroll
                    for (int q = 0; q < 8; q++)
                        acc2[q] = ffma2(win[dj + q], wp, acc2[q]);
                }
            }
        }
    }

    const float bias = b2[0];
    float res[8];
    #pragma unroll
    for (int q = 0; q < 8; q++) {
        float2 r = unpk(acc2[q]);
        int j = j0 + jq + q;
        res[q] = (i < plen && j < plen) ? (r.x + r.y + bias) : 0.f;
    }
    outp[0] = make_float4(res[0], res[1], res[2], res[3]);
    outp[1] = make_float4(res[4], res[5], res[6], res[7]);
}

// ============================================================
extern "C" void kernel_launch(void* const* d_in, const int* in_sizes, int n_in,
                              void* d_out, int out_size) {
    const float* x  = (const float*)d_in[0];   // [8,256,256] f32
    const int*   pl = (const int*)  d_in[1];   // [8] i32
    const float* W1 = (const float*)d_in[2];   // [512,32] f32
    const float* b1 = (const float*)d_in[3];   // [32] f32
    const float* W2 = (const float*)d_in[4];   // [7,7,32,1] f32
    const float* b2 = (const float*)d_in[5];   // [1] f32
    float* out = (float*)d_out;                // [8,256,256,1] f32

    const int smem1 = (8192 + 48 * 257) * 4;             // 82112 B
    const int smem2 = 1568 * 4 + 4 * S2_PL * 8;          // 6272 + 51072 = 57344 B
    cudaFuncSetAttribute(stage1_kernel, cudaFuncAttributeMaxDynamicSharedMemorySize, smem1);
    cudaFuncSetAttribute(stage2_kernel, cudaFuncAttributeMaxDynamicSharedMemorySize, smem2);

    dim3 g1(8, 16, 8);    // j-tiles, i-tiles, batch
    stage1_kernel<<<g1, 128, smem1>>>(x, pl, W1, b1);
    dim3 g2(8, 8, 8);
    stage2_kernel<<<g2, 128, smem2>>>(pl, W2, b2, out);
}